// round 15
// baseline (speedup 1.0000x reference)
#include <cuda_runtime.h>
#include <cuda_bf16.h>
#include <stdint.h>
#include <math.h>

#define NMAX 100000
#define EMAX 1600000

// ---------------- scratch (allocation-free: __device__ globals) ----------------
__device__ float    g_bufA[(size_t)NMAX * 128];
__device__ float    g_bufB[(size_t)NMAX * 128];
__device__ float    g_deg[NMAX];
__device__ float    g_dinv[NMAX];
__device__ int      g_cnt[NMAX];
__device__ int      g_fill[NMAX];
__device__ int      g_rowptr[NMAX + 1];
__device__ int      g_col[EMAX];
__device__ float    g_coef[EMAX];
__device__ int      g_csum[128];
__device__ float    g_sum[128];
__device__ float    g_sumsq[128];
__device__ float    g_scale[128];
__device__ float    g_shift[128];
// fragment-ordered split weights: tile (nTile,kTile) of 64 words; stride 8192/layer
__device__ uint32_t g_wh[3 * 128 * 64];
__device__ uint32_t g_wl[3 * 128 * 64];
// fragment-ordered split activations: tile (rowTile,kTile) of 128 words
__device__ uint32_t g_hh[(size_t)NMAX * 64];
__device__ uint32_t g_hl[(size_t)NMAX * 64];

__device__ __forceinline__ const float* sel_src(int s, const float* ext) {
    return (s == 0) ? ext : ((s == 1) ? g_bufA : g_bufB);
}
__device__ __forceinline__ float* sel_dst(int s, float* ext) {
    return (s == 0) ? ext : ((s == 1) ? g_bufA : g_bufB);
}

__device__ __forceinline__ void split_bf16(float f, __nv_bfloat16& h, __nv_bfloat16& l) {
    h = __float2bfloat16(f);
    l = __float2bfloat16(f - __bfloat162float(h));
}
__device__ __forceinline__ uint32_t pack_bf16(__nv_bfloat16 a, __nv_bfloat16 b) {
    return (uint32_t)__bfloat16_as_ushort(a) | ((uint32_t)__bfloat16_as_ushort(b) << 16);
}

// ---------------- weight pre-split/transpose/pack into B-fragment order ----------------
// W [K=128][NC] fp32.  B-frag tile = 8 cols x 8 kwords (64 words):
//   lane l owns words j0:(c=l>>2, w=l&3), j1:(c=l>>2, w=(l&3)+4); idx = l*2 + j.
__global__ void k_packw(const float* __restrict__ W, int NC, int woff) {
    int idx = blockIdx.x * blockDim.x + threadIdx.x;
    if (idx >= NC * 64) return;
    int nn = idx >> 6;          // col
    int kk = idx & 63;          // k-word
    float a = W[(size_t)(2 * kk)     * NC + nn];
    float b = W[(size_t)(2 * kk + 1) * NC + nn];
    __nv_bfloat16 ha, la, hb, lb;
    split_bf16(a, ha, la);
    split_bf16(b, hb, lb);
    int nTile = nn >> 3, kTile = kk >> 3, cp = nn & 7, wp = kk & 7;
    int off = woff + ((nTile * 8 + kTile) << 6) + (cp * 4 + (wp & 3)) * 2 + (wp >> 2);
    g_wh[off] = pack_bf16(ha, hb);
    g_wl[off] = pack_bf16(la, lb);
}

// ---------------- activation BN+ReLU+split+pack into A-fragment order ----------------
// A-frag tile = 16 rows x 8 kwords (128 words):
//   lane l owns j0:(r=l>>2,w=l&3) j1:(r+8,w) j2:(r,w+4) j3:(r+8,w+4); idx = l*4 + j.
__global__ void k_bnsplit(const float* __restrict__ Xext, int xsel, int useBN, int n, int npad) {
    int idx = blockIdx.x * blockDim.x + threadIdx.x;   // over npad*32 float4s
    if (idx >= npad * 32) return;
    int r  = idx >> 5;
    int c4 = idx & 31;
    float4 v = make_float4(0.f, 0.f, 0.f, 0.f);
    if (r < n) {
        const float4* X4 = (const float4*)sel_src(xsel, Xext);
        v = X4[idx];
        if (useBN) {
            int k = c4 * 4;
            v.x = fmaxf(fmaf(v.x, g_scale[k],     g_shift[k]),     0.f);
            v.y = fmaxf(fmaf(v.y, g_scale[k + 1], g_shift[k + 1]), 0.f);
            v.z = fmaxf(fmaf(v.z, g_scale[k + 2], g_shift[k + 2]), 0.f);
            v.w = fmaxf(fmaf(v.w, g_scale[k + 3], g_shift[k + 3]), 0.f);
        }
    }
    __nv_bfloat16 h0,l0,h1,l1,h2,l2,h3,l3;
    split_bf16(v.x, h0, l0); split_bf16(v.y, h1, l1);
    split_bf16(v.z, h2, l2); split_bf16(v.w, h3, l3);
    int w0 = 2 * c4;                       // even k-word; w0+1 same j, l+1
    int rowTile = r >> 4, kTile = w0 >> 3, rp = r & 15, wp = w0 & 7;
    size_t off = ((size_t)(rowTile * 8 + kTile) << 7)
               + (size_t)(((rp & 7) * 4 + (wp & 3)) * 4 + (rp >> 3) + ((wp >> 2) << 1));
    g_hh[off]     = pack_bf16(h0, h1);
    g_hh[off + 4] = pack_bf16(h2, h3);
    g_hl[off]     = pack_bf16(l0, l1);
    g_hl[off + 4] = pack_bf16(l2, l3);
}

// ---------------- graph preprocessing ----------------
__global__ void k_init(int n) {
    int v = blockIdx.x * blockDim.x + threadIdx.x;
    if (v < n) { g_deg[v] = 1.0f; g_cnt[v] = 0; g_fill[v] = 0; }
    if (v < 128) { g_sum[v] = 0.f; g_sumsq[v] = 0.f; }
}

__global__ void k_hist(const int* __restrict__ ei, const float* __restrict__ w, int E, int n) {
    int e = blockIdx.x * blockDim.x + threadIdx.x;
    if (e < E) {
        int dst = ei[E + e];
        if ((unsigned)dst < (unsigned)n) {
            atomicAdd(&g_deg[dst], w[e]);
            atomicAdd(&g_cnt[dst], 1);
        }
    }
}

__global__ void k_scanA(int n) {
    __shared__ int sh[1024];
    int t = threadIdx.x;
    int idx = blockIdx.x * 1024 + t;
    if (idx < n) g_dinv[idx] = rsqrtf(g_deg[idx]);
    sh[t] = (idx < n) ? g_cnt[idx] : 0;
    __syncthreads();
    for (int off = 512; off > 0; off >>= 1) {
        if (t < off) sh[t] += sh[t + off];
        __syncthreads();
    }
    if (t == 0) g_csum[blockIdx.x] = sh[0];
}

__global__ void k_scanB(int nc, int n) {
    __shared__ int sh[128];
    int t = threadIdx.x;
    int v = (t < nc) ? g_csum[t] : 0;
    sh[t] = v; __syncthreads();
    for (int off = 1; off < 128; off <<= 1) {
        int x = (t >= off) ? sh[t - off] : 0;
        __syncthreads();
        sh[t] += x;
        __syncthreads();
    }
    if (t < nc) g_csum[t] = sh[t] - v;
    if (t == nc - 1) g_rowptr[n] = sh[t];
}

__global__ void k_scanC(int n) {
    __shared__ int sh[1024];
    int t = threadIdx.x;
    int idx = blockIdx.x * 1024 + t;
    int val = (idx < n) ? g_cnt[idx] : 0;
    sh[t] = val; __syncthreads();
    for (int off = 1; off < 1024; off <<= 1) {
        int x = (t >= off) ? sh[t - off] : 0;
        __syncthreads();
        sh[t] += x;
        __syncthreads();
    }
    if (idx < n) g_rowptr[idx] = g_csum[blockIdx.x] + sh[t] - val;
}

__global__ void k_fill(const int* __restrict__ ei, const float* __restrict__ w, int E, int n) {
    int e = blockIdx.x * blockDim.x + threadIdx.x;
    if (e < E) {
        int s = ei[e];
        int d = ei[E + e];
        if ((unsigned)s < (unsigned)n && (unsigned)d < (unsigned)n) {
            int pos = g_rowptr[d] + atomicAdd(&g_fill[d], 1);
            g_col[pos]  = s;
            g_coef[pos] = g_dinv[s] * w[e] * g_dinv[d];
        }
    }
}

// ---------------- tensor-core GEMM: smem-free, fragment-ordered global loads ----------------
// O = Xh*Wh + Xh*Wl + Xl*Wh.

__device__ __forceinline__ void mma16816(float* d, const uint32_t* a, const uint32_t* b) {
    asm volatile(
        "mma.sync.aligned.m16n8k16.row.col.f32.bf16.bf16.f32 "
        "{%0,%1,%2,%3}, {%4,%5,%6,%7}, {%8,%9}, {%0,%1,%2,%3};\n"
        : "+f"(d[0]), "+f"(d[1]), "+f"(d[2]), "+f"(d[3])
        : "r"(a[0]), "r"(a[1]), "r"(a[2]), "r"(a[3]), "r"(b[0]), "r"(b[1]));
}

template<int NC>
__global__ void __launch_bounds__(256, 2)
k_gemm(int wsel, int osel, float* __restrict__ Oext, int n) {
    float* O = sel_dst(osel, Oext);
    const uint32_t* __restrict__ Wh = g_wh + wsel * 8192;
    const uint32_t* __restrict__ Wl = g_wl + wsel * 8192;

    const int t    = threadIdx.x;
    const int wid  = t >> 5;
    const int lane = t & 31;
    const int qr   = lane >> 2;
    const int qc   = (lane & 3) * 2;
    const int rowBase = blockIdx.x * 128;

    constexpr int M_TILES = (NC == 128) ? 2 : 1;
    const int mrow0 = (NC == 128) ? ((wid & 3) * 32) : (wid * 16);
    const int ncol0 = (NC == 128) ? ((wid >> 2) * 64) : 0;
    const int aTile0 = blockIdx.x * 8 + (mrow0 >> 4);    // first 16-row tile index
    const int nTile0 = ncol0 >> 3;

    float d[M_TILES][8][4];
    #pragma unroll
    for (int mt = 0; mt < M_TILES; mt++)
        #pragma unroll
        for (int nt = 0; nt < 8; nt++)
            #pragma unroll
            for (int j = 0; j < 4; j++) d[mt][nt][j] = 0.f;

    #pragma unroll
    for (int kt = 0; kt < 8; kt++) {
        uint4 ah4[M_TILES], al4[M_TILES];
        #pragma unroll
        for (int mt = 0; mt < M_TILES; mt++) {
            size_t aoff = ((size_t)(aTile0 + mt) * 8 + kt) * 128 + lane * 4;
            ah4[mt] = *(const uint4*)&g_hh[aoff];
            al4[mt] = *(const uint4*)&g_hl[aoff];
        }
        #pragma unroll
        for (int nt = 0; nt < 8; nt++) {
            size_t boff = ((size_t)(nTile0 + nt) * 8 + kt) * 64 + lane * 2;
            uint2 bh2 = *(const uint2*)&Wh[boff];
            uint2 bl2 = *(const uint2*)&Wl[boff];
            #pragma unroll
            for (int mt = 0; mt < M_TILES; mt++) {
                mma16816(d[mt][nt], (const uint32_t*)&ah4[mt], (const uint32_t*)&bh2);
                mma16816(d[mt][nt], (const uint32_t*)&ah4[mt], (const uint32_t*)&bl2);
                mma16816(d[mt][nt], (const uint32_t*)&al4[mt], (const uint32_t*)&bh2);
            }
        }
    }

    // ---- epilogue ----
    #pragma unroll
    for (int mt = 0; mt < M_TILES; mt++) {
        #pragma unroll
        for (int nt = 0; nt < 8; nt++) {
            int r = rowBase + mrow0 + mt * 16 + qr;
            int c = ncol0 + nt * 8 + qc;
            if (r < n)
                *(float2*)&O[(size_t)r * NC + c] = make_float2(d[mt][nt][0], d[mt][nt][1]);
            if (r + 8 < n)
                *(float2*)&O[(size_t)(r + 8) * NC + c] = make_float2(d[mt][nt][2], d[mt][nt][3]);
        }
    }
}

// ---------------- aggregation: out[v] = sum_in coef*h[src] + dinv[v]^2*h[v] + bias ----------------
template<int D>
__global__ void k_agg(int hsel, const float* __restrict__ bias,
                      float* __restrict__ Oext, int osel, int n) {
    const int TPN = D / 4;
    const int NPB = 256 / TPN;
    int t    = threadIdx.x;
    int v    = blockIdx.x * NPB + t / TPN;
    int lane = t % TPN;
    if (v >= n) return;

    const float4* H4 = (const float4*)sel_src(hsel, nullptr);
    float4*       O4 = (float4*)sel_dst(osel, Oext);

    float dv = g_dinv[v];
    float sc = dv * dv;
    float4 h = H4[(size_t)v * TPN + lane];
    float4 acc  = make_float4(h.x * sc, h.y * sc, h.z * sc, h.w * sc);
    float4 acc2 = make_float4(0.f, 0.f, 0.f, 0.f);

    int p   = g_rowptr[v];
    int end = g_rowptr[v + 1];
    for (; p + 4 <= end; p += 4) {
        int c0 = g_col[p];     float w0 = g_coef[p];
        int c1 = g_col[p + 1]; float w1 = g_coef[p + 1];
        int c2 = g_col[p + 2]; float w2 = g_coef[p + 2];
        int c3 = g_col[p + 3]; float w3 = g_coef[p + 3];
        float4 m0 = H4[(size_t)c0 * TPN + lane];
        float4 m1 = H4[(size_t)c1 * TPN + lane];
        float4 m2 = H4[(size_t)c2 * TPN + lane];
        float4 m3 = H4[(size_t)c3 * TPN + lane];
        acc.x  = fmaf(w0, m0.x, acc.x);  acc.y  = fmaf(w0, m0.y, acc.y);
        acc.z  = fmaf(w0, m0.z, acc.z);  acc.w  = fmaf(w0, m0.w, acc.w);
        acc2.x = fmaf(w1, m1.x, acc2.x); acc2.y = fmaf(w1, m1.y, acc2.y);
        acc2.z = fmaf(w1, m1.z, acc2.z); acc2.w = fmaf(w1, m1.w, acc2.w);
        acc.x  = fmaf(w2, m2.x, acc.x);  acc.y  = fmaf(w2, m2.y, acc.y);
        acc.z  = fmaf(w2, m2.z, acc.z);  acc.w  = fmaf(w2, m2.w, acc.w);
        acc2.x = fmaf(w3, m3.x, acc2.x); acc2.y = fmaf(w3, m3.y, acc2.y);
        acc2.z = fmaf(w3, m3.z, acc2.z); acc2.w = fmaf(w3, m3.w, acc2.w);
    }
    for (; p < end; p++) {
        int c = g_col[p]; float w = g_coef[p];
        float4 m = H4[(size_t)c * TPN + lane];
        acc.x = fmaf(w, m.x, acc.x); acc.y = fmaf(w, m.y, acc.y);
        acc.z = fmaf(w, m.z, acc.z); acc.w = fmaf(w, m.w, acc.w);
    }
    acc.x += acc2.x; acc.y += acc2.y; acc.z += acc2.z; acc.w += acc2.w;

    float4 b4 = ((const float4*)bias)[lane];
    acc.x += b4.x; acc.y += b4.y; acc.z += b4.z; acc.w += b4.w;
    O4[(size_t)v * TPN + lane] = acc;
}

// ---------------- BatchNorm stats / finalize (stats always on g_bufB) ----------------
__global__ void k_stats(int n) {
    int t = threadIdx.x;
    int col = t & 127;
    int phase = t >> 7;
    float s = 0.f, sq = 0.f;
    for (int r = blockIdx.x * 2 + phase; r < n; r += gridDim.x * 2) {
        float v = g_bufB[(size_t)r * 128 + col];
        s += v; sq += v * v;
    }
    __shared__ float ssum[256], ssq[256];
    ssum[t] = s; ssq[t] = sq;
    __syncthreads();
    if (t < 128) {
        atomicAdd(&g_sum[t],   ssum[t] + ssum[t + 128]);
        atomicAdd(&g_sumsq[t], ssq[t]  + ssq[t + 128]);
    }
}

__global__ void k_bnfin(const float* __restrict__ gamma, const float* __restrict__ beta, int n) {
    int c = threadIdx.x;
    double mean = (double)g_sum[c] / (double)n;
    double var  = (double)g_sumsq[c] / (double)n - mean * mean;
    float s = (float)((double)gamma[c] / sqrt(var + 1e-5));
    g_scale[c] = s;
    g_shift[c] = (float)((double)beta[c] - mean * (double)s);
    g_sum[c] = 0.f;
    g_sumsq[c] = 0.f;
}

// ---------------- launcher ----------------
extern "C" void kernel_launch(void* const* d_in, const int* in_sizes, int n_in,
                              void* d_out, int out_size) {
    const float* x  = (const float*)d_in[0];
    const int*   ei = (const int*)d_in[1];     // int32 [2, E]
    const float* w  = (const float*)d_in[2];
    const float* W1 = (const float*)d_in[3];
    const float* b1 = (const float*)d_in[4];
    const float* W2 = (const float*)d_in[5];
    const float* b2 = (const float*)d_in[6];
    const float* W3 = (const float*)d_in[7];
    const float* b3 = (const float*)d_in[8];
    const float* gamma1 = (const float*)d_in[9];
    const float* beta1  = (const float*)d_in[10];
    const float* gamma2 = (const float*)d_in[11];
    const float* beta2  = (const float*)d_in[12];

    int n = in_sizes[0] / 128;
    int E = in_sizes[1] / 2;
    float* out = (float*)d_out;

    int npad = (n + 15) & ~15;
    int nb_n = (n + 255) / 256;
    int nb_e = (E + 255) / 256;
    int nc   = (n + 1023) / 1024;
    int gemm_grid  = (n + 127) / 128;
    int split_grid = (npad * 32 + 255) / 256;

    // order chosen so the profiled launch (index 3) is k_gemm<128> layer 1
    k_packw<<<(128 * 64 + 255) / 256, 256>>>(W1, 128, 0);        // 0
    k_bnsplit<<<split_grid, 256>>>(x, 0, 0, n, npad);            // 1
    k_packw<<<(128 * 64 + 255) / 256, 256>>>(W2, 128, 8192);     // 2
    k_gemm<128><<<gemm_grid, 256>>>(0, 1, nullptr, n);           // 3  <- profiled
    k_packw<<<(64 * 64 + 255) / 256, 256>>>(W3, 64, 16384);      // 4

    // graph preprocessing (CSR by dst + normalization coefs)
    k_init<<<nb_n, 256>>>(n);
    k_hist<<<nb_e, 256>>>(ei, w, E, n);
    k_scanA<<<nc, 1024>>>(n);              // also computes dinv
    k_scanB<<<1, 128>>>(nc, n);
    k_scanC<<<nc, 1024>>>(n);
    k_fill<<<nb_e, 256>>>(ei, w, E, n);

    // layer 1 (gemm already done): agg -> bufB, stats
    k_agg<128><<<(n + 7) / 8, 256>>>(1, b1, nullptr, 2, n);
    k_stats<<<400, 256>>>(n);
    k_bnfin<<<1, 128>>>(gamma1, beta1, n);

    // layer 2
    k_bnsplit<<<split_grid, 256>>>(nullptr, 2, 1, n, npad);
    k_gemm<128><<<gemm_grid, 256>>>(1, 1, nullptr, n);
    k_agg<128><<<(n + 7) / 8, 256>>>(1, b2, nullptr, 2, n);
    k_stats<<<400, 256>>>(n);
    k_bnfin<<<1, 128>>>(gamma2, beta2, n);

    // layer 3 (64 cols)
    k_bnsplit<<<split_grid, 256>>>(nullptr, 2, 1, n, npad);
    k_gemm<64><<<gemm_grid, 256>>>(2, 1, nullptr, n);
    k_agg<64><<<(n + 15) / 16, 256>>>(1, b3, out, 0, n);
}

// round 16
// speedup vs baseline: 1.1784x; 1.1784x over previous
#include <cuda_runtime.h>
#include <cuda_bf16.h>
#include <stdint.h>
#include <math.h>

#define NMAX 100000
#define EMAX 1600000

// ---------------- scratch (allocation-free: __device__ globals) ----------------
__device__ float    g_bufA[(size_t)NMAX * 128];
__device__ float    g_bufB[(size_t)NMAX * 128];
__device__ float    g_deg[NMAX];
__device__ float    g_dinv[NMAX];
__device__ int      g_cnt[NMAX];
__device__ int      g_fill[NMAX];
__device__ int      g_rowptr[NMAX + 1];
__device__ int      g_col[EMAX];
__device__ float    g_coef[EMAX];
__device__ int      g_csum[128];
__device__ float    g_sum[128];
__device__ float    g_sumsq[128];
__device__ float    g_scale[128];
__device__ float    g_shift[128];
// fragment-ordered split weights: tile (nTile,kTile) of 64 words; stride 8192/layer
__device__ uint32_t g_wh[3 * 128 * 64];
__device__ uint32_t g_wl[3 * 128 * 64];
// fragment-ordered split activations, padded so GEMM tile reads stay in bounds
__device__ uint32_t g_hh[(size_t)(NMAX + 128) * 64];
__device__ uint32_t g_hl[(size_t)(NMAX + 128) * 64];

__device__ __forceinline__ const float* sel_src(int s, const float* ext) {
    return (s == 0) ? ext : ((s == 1) ? g_bufA : g_bufB);
}
__device__ __forceinline__ float* sel_dst(int s, float* ext) {
    return (s == 0) ? ext : ((s == 1) ? g_bufA : g_bufB);
}

__device__ __forceinline__ void split_bf16(float f, __nv_bfloat16& h, __nv_bfloat16& l) {
    h = __float2bfloat16(f);
    l = __float2bfloat16(f - __bfloat162float(h));
}
__device__ __forceinline__ uint32_t pack_bf16(__nv_bfloat16 a, __nv_bfloat16 b) {
    return (uint32_t)__bfloat16_as_ushort(a) | ((uint32_t)__bfloat16_as_ushort(b) << 16);
}

// ---------------- weight pre-split/transpose/pack into B-fragment order ----------------
__global__ void k_packw(const float* __restrict__ W, int NC, int woff) {
    int idx = blockIdx.x * blockDim.x + threadIdx.x;
    if (idx >= NC * 64) return;
    int nn = idx >> 6;          // col
    int kk = idx & 63;          // k-word
    float a = W[(size_t)(2 * kk)     * NC + nn];
    float b = W[(size_t)(2 * kk + 1) * NC + nn];
    __nv_bfloat16 ha, la, hb, lb;
    split_bf16(a, ha, la);
    split_bf16(b, hb, lb);
    int nTile = nn >> 3, kTile = kk >> 3, cp = nn & 7, wp = kk & 7;
    int off = woff + ((nTile * 8 + kTile) << 6) + (cp * 4 + (wp & 3)) * 2 + (wp >> 2);
    g_wh[off] = pack_bf16(ha, hb);
    g_wl[off] = pack_bf16(la, lb);
}

// ---------------- activation BN+ReLU+split+pack into A-fragment order ----------------
__global__ void k_bnsplit(const float* __restrict__ Xext, int xsel, int useBN, int n, int npad) {
    int idx = blockIdx.x * blockDim.x + threadIdx.x;   // over npad*32 float4s
    if (idx >= npad * 32) return;
    int r  = idx >> 5;
    int c4 = idx & 31;
    float4 v = make_float4(0.f, 0.f, 0.f, 0.f);
    if (r < n) {
        const float4* X4 = (const float4*)sel_src(xsel, Xext);
        v = X4[idx];
        if (useBN) {
            int k = c4 * 4;
            v.x = fmaxf(fmaf(v.x, g_scale[k],     g_shift[k]),     0.f);
            v.y = fmaxf(fmaf(v.y, g_scale[k + 1], g_shift[k + 1]), 0.f);
            v.z = fmaxf(fmaf(v.z, g_scale[k + 2], g_shift[k + 2]), 0.f);
            v.w = fmaxf(fmaf(v.w, g_scale[k + 3], g_shift[k + 3]), 0.f);
        }
    }
    __nv_bfloat16 h0,l0,h1,l1,h2,l2,h3,l3;
    split_bf16(v.x, h0, l0); split_bf16(v.y, h1, l1);
    split_bf16(v.z, h2, l2); split_bf16(v.w, h3, l3);
    int w0 = 2 * c4;
    int rowTile = r >> 4, kTile = w0 >> 3, rp = r & 15, wp = w0 & 7;
    size_t off = ((size_t)(rowTile * 8 + kTile) << 7)
               + (size_t)(((rp & 7) * 4 + (wp & 3)) * 4 + (rp >> 3) + ((wp >> 2) << 1));
    g_hh[off]     = pack_bf16(h0, h1);
    g_hh[off + 4] = pack_bf16(h2, h3);
    g_hl[off]     = pack_bf16(l0, l1);
    g_hl[off + 4] = pack_bf16(l2, l3);
}

// ---------------- graph preprocessing ----------------
__global__ void k_init(int n) {
    int v = blockIdx.x * blockDim.x + threadIdx.x;
    if (v < n) { g_deg[v] = 1.0f; g_cnt[v] = 0; g_fill[v] = 0; }
    if (v < 128) { g_sum[v] = 0.f; g_sumsq[v] = 0.f; }
}

__global__ void k_hist(const int* __restrict__ ei, const float* __restrict__ w, int E, int n) {
    int e = blockIdx.x * blockDim.x + threadIdx.x;
    if (e < E) {
        int dst = ei[E + e];
        if ((unsigned)dst < (unsigned)n) {
            atomicAdd(&g_deg[dst], w[e]);
            atomicAdd(&g_cnt[dst], 1);
        }
    }
}

__global__ void k_scanA(int n) {
    __shared__ int sh[1024];
    int t = threadIdx.x;
    int idx = blockIdx.x * 1024 + t;
    if (idx < n) g_dinv[idx] = rsqrtf(g_deg[idx]);
    sh[t] = (idx < n) ? g_cnt[idx] : 0;
    __syncthreads();
    for (int off = 512; off > 0; off >>= 1) {
        if (t < off) sh[t] += sh[t + off];
        __syncthreads();
    }
    if (t == 0) g_csum[blockIdx.x] = sh[0];
}

__global__ void k_scanB(int nc, int n) {
    __shared__ int sh[128];
    int t = threadIdx.x;
    int v = (t < nc) ? g_csum[t] : 0;
    sh[t] = v; __syncthreads();
    for (int off = 1; off < 128; off <<= 1) {
        int x = (t >= off) ? sh[t - off] : 0;
        __syncthreads();
        sh[t] += x;
        __syncthreads();
    }
    if (t < nc) g_csum[t] = sh[t] - v;
    if (t == nc - 1) g_rowptr[n] = sh[t];
}

__global__ void k_scanC(int n) {
    __shared__ int sh[1024];
    int t = threadIdx.x;
    int idx = blockIdx.x * 1024 + t;
    int val = (idx < n) ? g_cnt[idx] : 0;
    sh[t] = val; __syncthreads();
    for (int off = 1; off < 1024; off <<= 1) {
        int x = (t >= off) ? sh[t - off] : 0;
        __syncthreads();
        sh[t] += x;
        __syncthreads();
    }
    if (idx < n) g_rowptr[idx] = g_csum[blockIdx.x] + sh[t] - val;
}

__global__ void k_fill(const int* __restrict__ ei, const float* __restrict__ w, int E, int n) {
    int e = blockIdx.x * blockDim.x + threadIdx.x;
    if (e < E) {
        int s = ei[e];
        int d = ei[E + e];
        if ((unsigned)s < (unsigned)n && (unsigned)d < (unsigned)n) {
            int pos = g_rowptr[d] + atomicAdd(&g_fill[d], 1);
            g_col[pos]  = s;
            g_coef[pos] = g_dinv[s] * w[e] * g_dinv[d];
        }
    }
}

// ---------------- tensor-core GEMM: smem-free, fragment-ordered global loads ----------------
__device__ __forceinline__ void mma16816(float* d, const uint32_t* a, const uint32_t* b) {
    asm volatile(
        "mma.sync.aligned.m16n8k16.row.col.f32.bf16.bf16.f32 "
        "{%0,%1,%2,%3}, {%4,%5,%6,%7}, {%8,%9}, {%0,%1,%2,%3};\n"
        : "+f"(d[0]), "+f"(d[1]), "+f"(d[2]), "+f"(d[3])
        : "r"(a[0]), "r"(a[1]), "r"(a[2]), "r"(a[3]), "r"(b[0]), "r"(b[1]));
}

template<int NC>
__global__ void __launch_bounds__(256, 2)
k_gemm(int wsel, int osel, float* __restrict__ Oext, int n) {
    float* O = sel_dst(osel, Oext);
    const uint32_t* __restrict__ Wh = g_wh + wsel * 8192;
    const uint32_t* __restrict__ Wl = g_wl + wsel * 8192;

    const int t    = threadIdx.x;
    const int wid  = t >> 5;
    const int lane = t & 31;
    const int qr   = lane >> 2;
    const int qc   = (lane & 3) * 2;
    const int rowBase = blockIdx.x * 128;

    constexpr int M_TILES = (NC == 128) ? 2 : 1;
    const int mrow0 = (NC == 128) ? ((wid & 3) * 32) : (wid * 16);
    const int ncol0 = (NC == 128) ? ((wid >> 2) * 64) : 0;
    const int aTile0 = blockIdx.x * 8 + (mrow0 >> 4);
    const int nTile0 = ncol0 >> 3;

    float d[M_TILES][8][4];
    #pragma unroll
    for (int mt = 0; mt < M_TILES; mt++)
        #pragma unroll
        for (int nt = 0; nt < 8; nt++)
            #pragma unroll
            for (int j = 0; j < 4; j++) d[mt][nt][j] = 0.f;

    #pragma unroll
    for (int kt = 0; kt < 8; kt++) {
        uint4 ah4[M_TILES], al4[M_TILES];
        #pragma unroll
        for (int mt = 0; mt < M_TILES; mt++) {
            size_t aoff = ((size_t)(aTile0 + mt) * 8 + kt) * 128 + lane * 4;
            ah4[mt] = *(const uint4*)&g_hh[aoff];
            al4[mt] = *(const uint4*)&g_hl[aoff];
        }
        #pragma unroll
        for (int nt = 0; nt < 8; nt++) {
            size_t boff = ((size_t)(nTile0 + nt) * 8 + kt) * 64 + lane * 2;
            uint2 bh2 = *(const uint2*)&Wh[boff];
            uint2 bl2 = *(const uint2*)&Wl[boff];
            #pragma unroll
            for (int mt = 0; mt < M_TILES; mt++) {
                mma16816(d[mt][nt], (const uint32_t*)&ah4[mt], (const uint32_t*)&bh2);
                mma16816(d[mt][nt], (const uint32_t*)&ah4[mt], (const uint32_t*)&bl2);
                mma16816(d[mt][nt], (const uint32_t*)&al4[mt], (const uint32_t*)&bh2);
            }
        }
    }

    #pragma unroll
    for (int mt = 0; mt < M_TILES; mt++) {
        #pragma unroll
        for (int nt = 0; nt < 8; nt++) {
            int r = rowBase + mrow0 + mt * 16 + qr;
            int c = ncol0 + nt * 8 + qc;
            if (r < n)
                *(float2*)&O[(size_t)r * NC + c] = make_float2(d[mt][nt][0], d[mt][nt][1]);
            if (r + 8 < n)
                *(float2*)&O[(size_t)(r + 8) * NC + c] = make_float2(d[mt][nt][2], d[mt][nt][3]);
        }
    }
}

// ---------------- aggregation (grid-stride group-per-node) + optional fused BN stats ----
// out[v] = sum_in coef*h[src] + dinv[v]^2*h[v] + bias; TPN = D/4 lanes per node.
template<int D, int STATS>
__global__ void k_agg(int hsel, const float* __restrict__ bias,
                      float* __restrict__ Oext, int osel, int n, int ngroups) {
    const int TPN = D / 4;
    const int GPB = 256 / TPN;
    __shared__ float ss[128], sq[128];
    int t = threadIdx.x;
    if (STATS) {
        if (t < 128) { ss[t] = 0.f; sq[t] = 0.f; }
        __syncthreads();
    }
    int lane  = t % TPN;
    int group = blockIdx.x * GPB + t / TPN;

    const float4* H4 = (const float4*)sel_src(hsel, nullptr);
    float4*       O4 = (float4*)sel_dst(osel, Oext);
    float4 b4 = ((const float4*)bias)[lane];

    float4 psum = make_float4(0.f, 0.f, 0.f, 0.f);
    float4 psq  = make_float4(0.f, 0.f, 0.f, 0.f);

    for (int v = group; v < n; v += ngroups) {
        float dv = g_dinv[v];
        float sc = dv * dv;
        float4 h = H4[(size_t)v * TPN + lane];
        float4 acc  = make_float4(h.x * sc, h.y * sc, h.z * sc, h.w * sc);
        float4 acc2 = make_float4(0.f, 0.f, 0.f, 0.f);

        int p   = g_rowptr[v];
        int end = g_rowptr[v + 1];
        for (; p + 4 <= end; p += 4) {
            int c0 = g_col[p];     float w0 = g_coef[p];
            int c1 = g_col[p + 1]; float w1 = g_coef[p + 1];
            int c2 = g_col[p + 2]; float w2 = g_coef[p + 2];
            int c3 = g_col[p + 3]; float w3 = g_coef[p + 3];
            float4 m0 = H4[(size_t)c0 * TPN + lane];
            float4 m1 = H4[(size_t)c1 * TPN + lane];
            float4 m2 = H4[(size_t)c2 * TPN + lane];
            float4 m3 = H4[(size_t)c3 * TPN + lane];
            acc.x  = fmaf(w0, m0.x, acc.x);  acc.y  = fmaf(w0, m0.y, acc.y);
            acc.z  = fmaf(w0, m0.z, acc.z);  acc.w  = fmaf(w0, m0.w, acc.w);
            acc2.x = fmaf(w1, m1.x, acc2.x); acc2.y = fmaf(w1, m1.y, acc2.y);
            acc2.z = fmaf(w1, m1.z, acc2.z); acc2.w = fmaf(w1, m1.w, acc2.w);
            acc.x  = fmaf(w2, m2.x, acc.x);  acc.y  = fmaf(w2, m2.y, acc.y);
            acc.z  = fmaf(w2, m2.z, acc.z);  acc.w  = fmaf(w2, m2.w, acc.w);
            acc2.x = fmaf(w3, m3.x, acc2.x); acc2.y = fmaf(w3, m3.y, acc2.y);
            acc2.z = fmaf(w3, m3.z, acc2.z); acc2.w = fmaf(w3, m3.w, acc2.w);
        }
        for (; p < end; p++) {
            int c = g_col[p]; float w = g_coef[p];
            float4 m = H4[(size_t)c * TPN + lane];
            acc.x = fmaf(w, m.x, acc.x); acc.y = fmaf(w, m.y, acc.y);
            acc.z = fmaf(w, m.z, acc.z); acc.w = fmaf(w, m.w, acc.w);
        }
        acc.x += acc2.x + b4.x; acc.y += acc2.y + b4.y;
        acc.z += acc2.z + b4.z; acc.w += acc2.w + b4.w;
        O4[(size_t)v * TPN + lane] = acc;

        if (STATS) {
            psum.x += acc.x; psum.y += acc.y; psum.z += acc.z; psum.w += acc.w;
            psq.x  = fmaf(acc.x, acc.x, psq.x); psq.y = fmaf(acc.y, acc.y, psq.y);
            psq.z  = fmaf(acc.z, acc.z, psq.z); psq.w = fmaf(acc.w, acc.w, psq.w);
        }
    }

    if (STATS) {
        int c0 = lane * 4;
        atomicAdd(&ss[c0],     psum.x); atomicAdd(&ss[c0 + 1], psum.y);
        atomicAdd(&ss[c0 + 2], psum.z); atomicAdd(&ss[c0 + 3], psum.w);
        atomicAdd(&sq[c0],     psq.x);  atomicAdd(&sq[c0 + 1], psq.y);
        atomicAdd(&sq[c0 + 2], psq.z);  atomicAdd(&sq[c0 + 3], psq.w);
        __syncthreads();
        if (t < 128) {
            atomicAdd(&g_sum[t],   ss[t]);
            atomicAdd(&g_sumsq[t], sq[t]);
        }
    }
}

// ---------------- BN finalize: scale/shift from stats, then reset stats ----------------
__global__ void k_bnfin(const float* __restrict__ gamma, const float* __restrict__ beta, int n) {
    int c = threadIdx.x;
    double mean = (double)g_sum[c] / (double)n;
    double var  = (double)g_sumsq[c] / (double)n - mean * mean;
    float s = (float)((double)gamma[c] / sqrt(var + 1e-5));
    g_scale[c] = s;
    g_shift[c] = (float)((double)beta[c] - mean * (double)s);
    g_sum[c] = 0.f;
    g_sumsq[c] = 0.f;
}

// ---------------- launcher ----------------
extern "C" void kernel_launch(void* const* d_in, const int* in_sizes, int n_in,
                              void* d_out, int out_size) {
    const float* x  = (const float*)d_in[0];
    const int*   ei = (const int*)d_in[1];     // int32 [2, E]
    const float* w  = (const float*)d_in[2];
    const float* W1 = (const float*)d_in[3];
    const float* b1 = (const float*)d_in[4];
    const float* W2 = (const float*)d_in[5];
    const float* b2 = (const float*)d_in[6];
    const float* W3 = (const float*)d_in[7];
    const float* b3 = (const float*)d_in[8];
    const float* gamma1 = (const float*)d_in[9];
    const float* beta1  = (const float*)d_in[10];
    const float* gamma2 = (const float*)d_in[11];
    const float* beta2  = (const float*)d_in[12];

    int n = in_sizes[0] / 128;
    int E = in_sizes[1] / 2;
    float* out = (float*)d_out;

    int npad = (n + 127) & ~127;                 // GEMM reads full 128-row tiles
    int nb_n = (n + 255) / 256;
    int nb_e = (E + 255) / 256;
    int nc   = (n + 1023) / 1024;
    int gemm_grid  = (n + 127) / 128;
    int split_grid = (npad * 32 + 255) / 256;

    const int AGG_BLOCKS = 1184;                 // 8 CTAs/SM target
    const int AGG_GROUPS128 = AGG_BLOCKS * 8;    // TPN=32 -> 8 groups/block
    const int AGG_BLOCKS64 = 592;
    const int AGG_GROUPS64 = AGG_BLOCKS64 * 16;  // TPN=16 -> 16 groups/block

    // order chosen so the profiled launch (index 3) is k_gemm<128> layer 1
    k_packw<<<(128 * 64 + 255) / 256, 256>>>(W1, 128, 0);        // 0
    k_bnsplit<<<split_grid, 256>>>(x, 0, 0, n, npad);            // 1
    k_packw<<<(128 * 64 + 255) / 256, 256>>>(W2, 128, 8192);     // 2
    k_gemm<128><<<gemm_grid, 256>>>(0, 1, nullptr, n);           // 3  <- profiled
    k_packw<<<(64 * 64 + 255) / 256, 256>>>(W3, 64, 16384);      // 4

    // graph preprocessing (CSR by dst + normalization coefs)
    k_init<<<nb_n, 256>>>(n);
    k_hist<<<nb_e, 256>>>(ei, w, E, n);
    k_scanA<<<nc, 1024>>>(n);
    k_scanB<<<1, 128>>>(nc, n);
    k_scanC<<<nc, 1024>>>(n);
    k_fill<<<nb_e, 256>>>(ei, w, E, n);

    // layer 1 (gemm already done): agg+stats -> bufB
    k_agg<128, 1><<<AGG_BLOCKS, 256>>>(1, b1, nullptr, 2, n, AGG_GROUPS128);
    k_bnfin<<<1, 128>>>(gamma1, beta1, n);

    // layer 2
    k_bnsplit<<<split_grid, 256>>>(nullptr, 2, 1, n, npad);
    k_gemm<128><<<gemm_grid, 256>>>(1, 1, nullptr, n);
    k_agg<128, 1><<<AGG_BLOCKS, 256>>>(1, b2, nullptr, 2, n, AGG_GROUPS128);
    k_bnfin<<<1, 128>>>(gamma2, beta2, n);

    // layer 3 (64 cols)
    k_bnsplit<<<split_grid, 256>>>(nullptr, 2, 1, n, npad);
    k_gemm<64><<<gemm_grid, 256>>>(2, 1, nullptr, n);
    k_agg<64, 0><<<AGG_BLOCKS64, 256>>>(1, b3, out, 0, n, AGG_GROUPS64);
}